// round 9
// baseline (speedup 1.0000x reference)
#include <cuda_runtime.h>
#include <cuda_fp16.h>
#include <math.h>

#define BB 16384
#define SS 16
#define NSTEPS 50
#define LATENT 128
#define HID 64
#define DTC 0.02f
#define SQRT_DT 0.14142135623730951f
#define LOG2E 1.4426950408889634f
#define LN2 0.6931471805599453f
#define EXPM50 1.9287498479639178e-22f /* exp(-50) */

typedef unsigned long long u64t;

// Scratch (no cudaMalloc allowed)
__device__ float g_zc[BB * HID];   // per-b hidden bias: z@W1[:,2:].T + b1
__device__ float g_halfb[BB];      // 0.5*boundary
__device__ float g_ndt[BB];        // non-decision time

__device__ __forceinline__ float ex2f(float v) {
    float r; asm("ex2.approx.f32 %0, %1;" : "=f"(r) : "f"(v)); return r;
}
__device__ __forceinline__ float lg2f(float v) {
    float r; asm("lg2.approx.f32 %0, %1;" : "=f"(r) : "f"(v)); return r;
}
__device__ __forceinline__ float tanhapx(float v) {
    float r; asm("tanh.approx.f32 %0, %1;" : "=f"(r) : "f"(v)); return r;
}
__device__ __forceinline__ half2 tanh2h(half2 x) {
    unsigned xi = *reinterpret_cast<unsigned*>(&x);
    unsigned r;
    asm("tanh.approx.f16x2 %0, %1;" : "=r"(r) : "r"(xi));
    return *reinterpret_cast<half2*>(&r);
}
__device__ __forceinline__ u64t pack2(float lo, float hi) {
    u64t r;
    asm("mov.b64 %0, {%1, %2};" : "=l"(r)
        : "r"(__float_as_uint(lo)), "r"(__float_as_uint(hi)));
    return r;
}
__device__ __forceinline__ void unpack2(u64t v, float& lo, float& hi) {
    unsigned a, b;
    asm("mov.b64 {%0, %1}, %2;" : "=r"(a), "=r"(b) : "l"(v));
    lo = __uint_as_float(a); hi = __uint_as_float(b);
}
__device__ __forceinline__ u64t fma2(u64t a, u64t b, u64t c) {
    u64t r; asm("fma.rn.f32x2 %0, %1, %2, %3;" : "=l"(r) : "l"(a), "l"(b), "l"(c));
    return r;
}
// Sum the two f16 halves of v as f32, using ALU-pipe bit-expansion
// (exact for normal f16; subnormals introduce <= 6.1e-5 abs error).
__device__ __forceinline__ float h2sum(half2 v) {
    unsigned r = *reinterpret_cast<unsigned*>(&v);
    unsigned lo = ((r << 16) & 0x80000000u) | (((r & 0x7FFFu) << 13) + 0x38000000u);
    unsigned hi = (r & 0x80000000u) | (((r >> 3) & 0x0FFFE000u) + 0x38000000u);
    return __uint_as_float(lo) + __uint_as_float(hi);
}
__device__ __forceinline__ float fix_out(float v) {
    if (isnan(v)) return 0.0f;
    return fminf(fmaxf(v, -3.402823466e38f), 3.402823466e38f);
}

// ---------------------------------------------------------------------------
// Precompute: zc[b][j] = b1[j] + sum_k z[b,k]*W1[j,2+k]; boundary & ndt per b.
// ---------------------------------------------------------------------------
__global__ __launch_bounds__(256) void precompute_kernel(
    const float* __restrict__ z,  const float* __restrict__ W1,
    const float* __restrict__ b1, const float* __restrict__ Wb,
    const float* __restrict__ bbv, const float* __restrict__ Wn,
    const float* __restrict__ bnv)
{
    __shared__ __align__(16) float sW[HID * 130];   // whole W1, 33.3KB
    __shared__ __align__(16) float sz[16 * LATENT]; // 16 z rows, 8KB
    const int tid = threadIdx.x;
    const int b0 = blockIdx.x * 16;

    for (int i = tid; i < HID * 130; i += 256) sW[i] = W1[i];
    for (int i = tid; i < 16 * LATENT; i += 256) sz[i] = z[b0 * LATENT + i];
    __syncthreads();

    const int j = tid & 63;
    const int bg = tid >> 6;   // 0..3, each handles 4 b's
    const float* wrow = sW + j * 130 + 2;
    float a0, a1, a2, a3;
    a0 = a1 = a2 = a3 = b1[j];
    const float* z0 = sz + (bg * 4 + 0) * LATENT;
    const float* z1 = sz + (bg * 4 + 1) * LATENT;
    const float* z2 = sz + (bg * 4 + 2) * LATENT;
    const float* z3 = sz + (bg * 4 + 3) * LATENT;
    #pragma unroll 8
    for (int k = 0; k < LATENT; k += 4) {
        float w0 = wrow[k], w1 = wrow[k + 1], w2 = wrow[k + 2], w3 = wrow[k + 3];
        float4 q0 = *(const float4*)(z0 + k);
        float4 q1 = *(const float4*)(z1 + k);
        float4 q2 = *(const float4*)(z2 + k);
        float4 q3 = *(const float4*)(z3 + k);
        a0 = fmaf(w0, q0.x, a0); a0 = fmaf(w1, q0.y, a0); a0 = fmaf(w2, q0.z, a0); a0 = fmaf(w3, q0.w, a0);
        a1 = fmaf(w0, q1.x, a1); a1 = fmaf(w1, q1.y, a1); a1 = fmaf(w2, q1.z, a1); a1 = fmaf(w3, q1.w, a1);
        a2 = fmaf(w0, q2.x, a2); a2 = fmaf(w1, q2.y, a2); a2 = fmaf(w2, q2.z, a2); a2 = fmaf(w3, q2.w, a2);
        a3 = fmaf(w0, q3.x, a3); a3 = fmaf(w1, q3.y, a3); a3 = fmaf(w2, q3.z, a3); a3 = fmaf(w3, q3.w, a3);
    }
    g_zc[(b0 + bg * 4 + 0) * HID + j] = a0;
    g_zc[(b0 + bg * 4 + 1) * HID + j] = a1;
    g_zc[(b0 + bg * 4 + 2) * HID + j] = a2;
    g_zc[(b0 + bg * 4 + 3) * HID + j] = a3;

    if (tid < 32) {
        const int bl = tid >> 1;
        const int isn = tid & 1;
        const float* wv = isn ? Wn : Wb;
        const float* zz = sz + bl * LATENT;
        float acc = isn ? bnv[0] : bbv[0];
        #pragma unroll 8
        for (int k = 0; k < LATENT; k++) acc = fmaf(wv[k], zz[k], acc);
        float sp = fmaxf(acc, 0.0f) + log1pf(expf(-fabsf(acc)));
        if (isn) g_ndt[b0 + bl] = sp + 0.05f;
        else     g_halfb[b0 + bl] = 0.5f * (sp + 0.3f);
    }
}

// ---------------------------------------------------------------------------
// Main SDE kernel. 4 lanes per (b,s); each lane owns 16 of 64 hidden units
// (8 f32x2 pairs). Single sim per lane -> low registers -> high occupancy.
// Inner layer: u in f32 (fma.f32x2), pack to f16x2 (F2FP, fma pipe), one
// tanh.approx.f16x2 per 2 units (MUFU), accumulate in f16 (HFMA2, fma pipe),
// final widening via ALU bit-trick. Block 128 = 2 b's x 16 sims x 4 reps.
// ---------------------------------------------------------------------------
__global__ __launch_bounds__(128, 5) void sde_kernel(
    const float* __restrict__ W1, const float* __restrict__ W2,
    const float* __restrict__ b2, const float* __restrict__ noise,
    const float* __restrict__ osc, const float* __restrict__ obi,
    float* __restrict__ out)
{
    const int tid = threadIdx.x;
    const int rep = tid & 3;          // which 16-unit slice
    const int s   = (tid >> 2) & 15;  // sim
    const int bl  = tid >> 6;         // 0..1
    const int b   = blockIdx.x * 2 + bl;
    const int jbase = rep * 16;

    u64t w1x2[8], w1t2[8], zc2[8];
    half2 w2a2[8], w2b2[8];
    #pragma unroll
    for (int p = 0; p < 8; p++) {
        const int j = jbase + p * 2;
        w1x2[p] = pack2(W1[j * 130],       W1[(j + 1) * 130]);
        w1t2[p] = pack2(W1[j * 130 + 1],   W1[(j + 1) * 130 + 1]);
        zc2[p]  = pack2(g_zc[b * HID + j], g_zc[b * HID + j + 1]);
        w2a2[p] = __floats2half2_rn(W2[j],       W2[j + 1]);
        w2b2[p] = __floats2half2_rn(W2[HID + j], W2[HID + j + 1]);
    }
    const float b2x = b2[0], b2y = b2[1];
    const float half_b = g_halfb[b];
    const half2 hzero = __floats2half2_rn(0.0f, 0.0f);

    float x = 0.0f, p_surv = 1.0f, exp_rt = 0.0f, exp_corr = 0.0f;
    const int nidx = b * SS + s;
    float nz = noise[nidx];

    #pragma unroll 1
    for (int k = 0; k < NSTEPS; k++) {
        const int k1 = (k + 1 < NSTEPS) ? (k + 1) : (NSTEPS - 1);
        const float nz_next = noise[k1 * (BB * SS) + nidx];  // prefetch
        const float tk = (float)k * DTC;
        const u64t tk2 = pack2(tk, tk);
        const u64t x2  = pack2(x, x);

        half2 da = hzero, db = hzero;
        #pragma unroll
        for (int p = 0; p < 8; p++) {
            u64t u2 = fma2(tk2, w1t2[p], zc2[p]);
            u2 = fma2(x2, w1x2[p], u2);
            float ulo, uhi; unpack2(u2, ulo, uhi);
            const half2 h = tanh2h(__floats2half2_rn(ulo, uhi));
            da = __hfma2(h, w2a2[p], da);
            db = __hfma2(h, w2b2[p], db);
        }
        float pd = h2sum(da);
        float pf = h2sum(db);
        pd += __shfl_xor_sync(0xffffffffu, pd, 1);
        pf += __shfl_xor_sync(0xffffffffu, pf, 1);
        pd += __shfl_xor_sync(0xffffffffu, pd, 2);
        pf += __shfl_xor_sync(0xffffffffu, pf, 2);

        const float dyn0 = pd + b2x;
        const float dyn1 = pf + b2y;
        const float drift = fminf(fmaxf(dyn0, -5.0f), 5.0f);
        // softplus(dyn1) = max(v,0) + ln(1 + e^{-|v|})
        const float e1 = ex2f(-fabsf(dyn1) * LOG2E);
        const float sp = fmaxf(dyn1, 0.0f) + lg2f(1.0f + e1) * LN2;
        const float diff = sp + 0.1f;

        x = fmaf(diff * SQRT_DT, nz, fmaf(drift, DTC, x));
        x = fminf(fmaxf(x, -10.0f), 10.0f);

        const float dist = fabsf(x) - half_b;
        // sigmoid(20*dist) = 0.5 + 0.5*tanh(10*dist)
        const float sg = fmaf(0.5f, tanhapx(10.0f * dist), 0.5f);
        const float hz = fminf(fmaxf(sg, 0.0f), 0.99f);
        const float sb = fmaxf(p_surv, EXPM50);
        const float cp = sb * hz;
        p_surv = p_surv * (1.0f - hz);
        exp_rt = fmaf(cp, tk + DTC, exp_rt);
        exp_corr += (x > 0.0f) ? cp : 0.0f;

        nz = nz_next;
    }

    const float rem = fmaxf(p_surv, EXPM50);
    exp_rt  = fmaf(rem, (float)NSTEPS * DTC, exp_rt);
    exp_corr = fmaf(rem, 0.5f, exp_corr);
    const float rt_ms = (exp_rt + g_ndt[b]) * 1000.0f;

    // per-b reduction over the 16 sims
    __shared__ float s_rt[2][16];
    __shared__ float s_cr[2][16];
    if (rep == 0) { s_rt[bl][s] = rt_ms; s_cr[bl][s] = exp_corr; }
    __syncthreads();

    if (tid < 2) {
        float m = 0.0f, c = 0.0f;
        #pragma unroll
        for (int i = 0; i < 16; i++) { m += s_rt[tid][i]; c += s_cr[tid][i]; }
        m *= (1.0f / 16.0f);
        c *= (1.0f / 16.0f);
        float v = 0.0f;
        #pragma unroll
        for (int i = 0; i < 16; i++) {
            float d = s_rt[tid][i] - m;
            v = fmaf(d, d, v);
        }
        const float sd = sqrtf(v * (1.0f / 15.0f));  // ddof=1
        const int bo = blockIdx.x * 2 + tid;
        const float o0 = m * osc[0] + obi[0];
        const float o1 = (sd + 0.001f) * osc[1] + obi[1];
        const float o2 = c * osc[2] + obi[2];
        out[bo * 3 + 0] = fix_out(o0);
        out[bo * 3 + 1] = fix_out(o1);
        out[bo * 3 + 2] = fix_out(o2);
    }
}

extern "C" void kernel_launch(void* const* d_in, const int* in_sizes, int n_in,
                              void* d_out, int out_size)
{
    const float* z   = (const float*)d_in[0];
    const float* W1  = (const float*)d_in[1];
    const float* b1  = (const float*)d_in[2];
    const float* W2  = (const float*)d_in[3];
    const float* b2  = (const float*)d_in[4];
    const float* Wb  = (const float*)d_in[5];
    const float* bbv = (const float*)d_in[6];
    const float* Wn  = (const float*)d_in[7];
    const float* bnv = (const float*)d_in[8];
    const float* osc = (const float*)d_in[9];
    const float* obi = (const float*)d_in[10];
    const float* noise = (const float*)d_in[11];
    float* out = (float*)d_out;

    precompute_kernel<<<BB / 16, 256>>>(z, W1, b1, Wb, bbv, Wn, bnv);
    sde_kernel<<<BB / 2, 128>>>(W1, W2, b2, noise, osc, obi, out);
}